// round 6
// baseline (speedup 1.0000x reference)
#include <cuda_runtime.h>
#include <cuda_fp16.h>
#include <cstdint>

// BitLinear: scale = mean|W|; Wq = round(W/(scale+eps)); y = (x @ Wq^T) * scale
// x: [8192, 4096] f32, W: [4096, 4096] f32, out: [8192, 4096] f32
//
// R4 (resubmit after infra failure): fp16-ACCUMULATE mma (2x rate vs fp32-acc)
// with per-stage (K=64) fp32 spill to bound rounding error. Operands
// pre-quantized fp16, pre-blocked + SW128-swizzled; single-thread
// cp.async.bulk producer, 3-stage mbarrier pipeline, 128x128x64 tiles,
// warp tile 64x32.

#define EPS_F 1e-5f

__device__ float  g_partial[4096];
__device__ float  g_scale;
__device__ float  g_inv;
// blocked+swizzled fp16 operands, 16KB blocks = [128 rows][64 halves] SW128
__device__ __align__(1024) __half g_Xa[8192u * 4096u];   // [64 m][64 k] blocks
__device__ __align__(1024) __half g_Wb[4096u * 4096u];   // [32 n][64 k] blocks

__host__ __device__ __forceinline__ uint32_t sw128(uint32_t off) {
    return off ^ ((off >> 3) & 0x70);
}

// ---------------------------------------------------------------- reductions
__global__ void k_absum_rows(const float* __restrict__ W) {
    int row = blockIdx.x;
    const float* p = W + (size_t)row * 4096;
    float s = 0.f;
    for (int i = threadIdx.x; i < 4096; i += 256) s += fabsf(p[i]);
    for (int o = 16; o > 0; o >>= 1) s += __shfl_down_sync(0xffffffffu, s, o);
    __shared__ float sm[8];
    if ((threadIdx.x & 31) == 0) sm[threadIdx.x >> 5] = s;
    __syncthreads();
    if (threadIdx.x < 8) {
        float v = sm[threadIdx.x];
        for (int o = 4; o > 0; o >>= 1) v += __shfl_down_sync(0xffu, v, o);
        if (threadIdx.x == 0) g_partial[row] = v;
    }
}

__global__ void k_finalize_scale() {
    float s = 0.f;
    for (int i = threadIdx.x; i < 4096; i += 256) s += g_partial[i];
    for (int o = 16; o > 0; o >>= 1) s += __shfl_down_sync(0xffffffffu, s, o);
    __shared__ float sm[8];
    if ((threadIdx.x & 31) == 0) sm[threadIdx.x >> 5] = s;
    __syncthreads();
    if (threadIdx.x < 8) {
        float v = sm[threadIdx.x];
        for (int o = 4; o > 0; o >>= 1) v += __shfl_down_sync(0xffu, v, o);
        if (threadIdx.x == 0) {
            float mean = v / 16777216.f;
            g_scale = mean;
            g_inv   = 1.f / (mean + EPS_F);
        }
    }
}

// ---------------------------------------------------------------- prepasses
__global__ void k_conv_x(const float4* __restrict__ X4) {
    int c  = blockIdx.x * 256 + threadIdx.x;
    int m  = c >> 9;
    int k8 = c & 511;
    const float4* src = X4 + (size_t)m * 1024 + k8 * 2;
    float4 v0 = src[0], v1 = src[1];
    __half2 h0 = __floats2half2_rn(v0.x, v0.y);
    __half2 h1 = __floats2half2_rn(v0.z, v0.w);
    __half2 h2 = __floats2half2_rn(v1.x, v1.y);
    __half2 h3 = __floats2half2_rn(v1.z, v1.w);
    uint4 u;
    u.x = *reinterpret_cast<uint32_t*>(&h0);
    u.y = *reinterpret_cast<uint32_t*>(&h1);
    u.z = *reinterpret_cast<uint32_t*>(&h2);
    u.w = *reinterpret_cast<uint32_t*>(&h3);
    int k   = k8 * 8;
    int blk = ((m >> 7) << 6) + (k >> 6);
    uint32_t off = ((m & 127) << 7) + ((k & 63) << 1);
    *reinterpret_cast<uint4*>((char*)g_Xa + (size_t)blk * 16384 + sw128(off)) = u;
}

__global__ void k_quant_w(const float4* __restrict__ W4) {
    float inv = g_inv;
    int c  = blockIdx.x * 256 + threadIdx.x;
    int o  = c >> 9;
    int k8 = c & 511;
    const float4* src = W4 + (size_t)o * 1024 + k8 * 2;
    float4 v0 = src[0], v1 = src[1];
    __half2 h0 = __floats2half2_rn(rintf(v0.x * inv), rintf(v0.y * inv));
    __half2 h1 = __floats2half2_rn(rintf(v0.z * inv), rintf(v0.w * inv));
    __half2 h2 = __floats2half2_rn(rintf(v1.x * inv), rintf(v1.y * inv));
    __half2 h3 = __floats2half2_rn(rintf(v1.z * inv), rintf(v1.w * inv));
    uint4 u;
    u.x = *reinterpret_cast<uint32_t*>(&h0);
    u.y = *reinterpret_cast<uint32_t*>(&h1);
    u.z = *reinterpret_cast<uint32_t*>(&h2);
    u.w = *reinterpret_cast<uint32_t*>(&h3);
    int k   = k8 * 8;
    int blk = ((o >> 7) << 6) + (k >> 6);
    uint32_t off = ((o & 127) << 7) + ((k & 63) << 1);
    *reinterpret_cast<uint4*>((char*)g_Wb + (size_t)blk * 16384 + sw128(off)) = u;
}

// ---------------------------------------------------------------- GEMM
__device__ __forceinline__ void mbar_init(uint32_t a, uint32_t cnt) {
    asm volatile("mbarrier.init.shared.b64 [%0], %1;" :: "r"(a), "r"(cnt) : "memory");
}
__device__ __forceinline__ void mbar_expect(uint32_t a, uint32_t bytes) {
    asm volatile("mbarrier.arrive.expect_tx.shared.b64 _, [%0], %1;"
                 :: "r"(a), "r"(bytes) : "memory");
}
__device__ __forceinline__ void mbar_wait(uint32_t a, uint32_t ph) {
    asm volatile(
        "{\n\t.reg .pred P;\n"
        "WL%=:\n\t"
        "mbarrier.try_wait.parity.shared.b64 P, [%0], %1, 0x989680;\n\t"
        "@P bra WD%=;\n\t"
        "bra WL%=;\n"
        "WD%=:\n\t}"
        :: "r"(a), "r"(ph) : "memory");
}
__device__ __forceinline__ void bulk_g2s(uint32_t dst, const void* src,
                                         uint32_t bytes, uint32_t mbar) {
    asm volatile(
        "cp.async.bulk.shared::cluster.global.mbarrier::complete_tx::bytes "
        "[%0], [%1], %2, [%3];"
        :: "r"(dst), "l"(src), "r"(bytes), "r"(mbar) : "memory");
}
__device__ __forceinline__ void ldm4(uint32_t addr, uint32_t& r0, uint32_t& r1,
                                     uint32_t& r2, uint32_t& r3) {
    asm volatile("ldmatrix.sync.aligned.m8n8.x4.shared.b16 {%0,%1,%2,%3}, [%4];"
                 : "=r"(r0), "=r"(r1), "=r"(r2), "=r"(r3) : "r"(addr));
}
// fp16-accumulate mma: D(f16x2 x2) = A*B + C
__device__ __forceinline__ void mma16816h(uint32_t& c0, uint32_t& c1,
                                          uint32_t a0, uint32_t a1, uint32_t a2, uint32_t a3,
                                          uint32_t b0, uint32_t b1) {
    asm volatile("mma.sync.aligned.m16n8k16.row.col.f16.f16.f16.f16 "
                 "{%0,%1},{%2,%3,%4,%5},{%6,%7},{%0,%1};"
                 : "+r"(c0), "+r"(c1)
                 : "r"(a0), "r"(a1), "r"(a2), "r"(a3), "r"(b0), "r"(b1));
}

#define NSTAGE 3
#define STG 16384
#define CTRL 1024
#define SMEM_TOTAL (CTRL + NSTAGE * 2 * STG)   // 99328

__global__ void __launch_bounds__(256) k_gemm(float* __restrict__ out) {
    extern __shared__ __align__(1024) char smem[];
    uint32_t sb = (uint32_t)__cvta_generic_to_shared(smem);
    const int tid    = threadIdx.x;
    const int lane   = tid & 31;
    const int wid    = tid >> 5;
    const int warp_m = wid >> 2;
    const int warp_n = wid & 3;
    const int bn     = blockIdx.x;   // 0..31
    const int bm     = blockIdx.y;   // 0..63

    const uint32_t sA = sb + CTRL;
    const uint32_t sB = sb + CTRL + NSTAGE * STG;
    const char* gA = (const char*)g_Xa + (size_t)bm * 64 * STG;
    const char* gB = (const char*)g_Wb + (size_t)bn * 64 * STG;

    if (tid == 0)
        for (int s = 0; s < NSTAGE; s++) mbar_init(sb + s * 8, 1);
    __syncthreads();

    if (tid == 0) {
#pragma unroll
        for (int j = 0; j < NSTAGE - 1; j++) {
            uint32_t fb = sb + j * 8;
            mbar_expect(fb, 2 * STG);
            bulk_g2s(sA + j * STG, gA + (size_t)j * STG, STG, fb);
            bulk_g2s(sB + j * STG, gB + (size_t)j * STG, STG, fb);
        }
    }

    float accf[4][4][4];
#pragma unroll
    for (int mi = 0; mi < 4; mi++)
#pragma unroll
        for (int ni = 0; ni < 4; ni++)
#pragma unroll
            for (int r = 0; r < 4; r++) accf[mi][ni][r] = 0.f;

    for (int i = 0; i < 64; ++i) {
        const int s = i % NSTAGE;
        mbar_wait(sb + s * 8, (i / NSTAGE) & 1);
        __syncthreads();
        if (tid == 0 && i + NSTAGE - 1 < 64) {
            int j = i + NSTAGE - 1;
            int t = j % NSTAGE;
            uint32_t fb = sb + t * 8;
            mbar_expect(fb, 2 * STG);
            bulk_g2s(sA + t * STG, gA + (size_t)j * STG, STG, fb);
            bulk_g2s(sB + t * STG, gB + (size_t)j * STG, STG, fb);
        }
        const uint32_t a_base = sA + s * STG;
        const uint32_t b_base = sB + s * STG;

        // fp16 window accumulators for this stage (K=64)
        uint32_t acch[4][4][2];
#pragma unroll
        for (int mi = 0; mi < 4; mi++)
#pragma unroll
            for (int ni = 0; ni < 4; ni++) {
                acch[mi][ni][0] = 0u;
                acch[mi][ni][1] = 0u;
            }

#pragma unroll
        for (int ks = 0; ks < 4; ++ks) {
            uint32_t a[4][4];
#pragma unroll
            for (int mi = 0; mi < 4; mi++) {
                int r   = warp_m * 64 + mi * 16 + (lane & 15);
                int col = ks * 16 + (lane >> 4) * 8;
                ldm4(a_base + sw128((uint32_t)(r * 128 + col * 2)),
                     a[mi][0], a[mi][1], a[mi][2], a[mi][3]);
            }
            uint32_t b[4][2];
#pragma unroll
            for (int np = 0; np < 2; np++) {
                int n   = warp_n * 32 + np * 16 + (lane >> 4) * 8 + (lane & 7);
                int col = ks * 16 + ((lane >> 3) & 1) * 8;
                uint32_t r0, r1, r2, r3;
                ldm4(b_base + sw128((uint32_t)(n * 128 + col * 2)), r0, r1, r2, r3);
                b[np * 2][0]     = r0;  b[np * 2][1]     = r1;
                b[np * 2 + 1][0] = r2;  b[np * 2 + 1][1] = r3;
            }
#pragma unroll
            for (int mi = 0; mi < 4; mi++)
#pragma unroll
                for (int ni = 0; ni < 4; ni++)
                    mma16816h(acch[mi][ni][0], acch[mi][ni][1],
                              a[mi][0], a[mi][1], a[mi][2], a[mi][3],
                              b[ni][0], b[ni][1]);
        }

        // spill window to fp32
#pragma unroll
        for (int mi = 0; mi < 4; mi++)
#pragma unroll
            for (int ni = 0; ni < 4; ni++) {
                float2 lo = __half22float2(*(__half2*)&acch[mi][ni][0]);
                float2 hi = __half22float2(*(__half2*)&acch[mi][ni][1]);
                accf[mi][ni][0] += lo.x;
                accf[mi][ni][1] += lo.y;
                accf[mi][ni][2] += hi.x;
                accf[mi][ni][3] += hi.y;
            }
    }

    const float scale = g_scale;
#pragma unroll
    for (int mi = 0; mi < 4; mi++) {
        int row0 = bm * 128 + warp_m * 64 + mi * 16 + (lane >> 2);
#pragma unroll
        for (int ni = 0; ni < 4; ni++) {
            int col = bn * 128 + warp_n * 32 + ni * 8 + (lane & 3) * 2;
            float2 v0 = make_float2(accf[mi][ni][0] * scale, accf[mi][ni][1] * scale);
            float2 v1 = make_float2(accf[mi][ni][2] * scale, accf[mi][ni][3] * scale);
            *(float2*)&out[(size_t)row0 * 4096 + col]       = v0;
            *(float2*)&out[(size_t)(row0 + 8) * 4096 + col] = v1;
        }
    }
}

// ---------------------------------------------------------------- launch
extern "C" void kernel_launch(void* const* d_in, const int* in_sizes, int n_in,
                              void* d_out, int out_size) {
    const float* x = (const float*)d_in[0];
    const float* W = (const float*)d_in[1];
    float* out = (float*)d_out;

    k_absum_rows<<<4096, 256>>>(W);
    k_finalize_scale<<<1, 256>>>();
    k_conv_x<<<16384, 256>>>((const float4*)x);
    k_quant_w<<<8192, 256>>>((const float4*)W);

    cudaFuncSetAttribute(k_gemm, cudaFuncAttributeMaxDynamicSharedMemorySize, SMEM_TOTAL);
    dim3 grid(32, 64);   // (N/128, M/128)
    k_gemm<<<grid, 256, SMEM_TOTAL>>>(out);
}

// round 9
// speedup vs baseline: 1.0466x; 1.0466x over previous
#include <cuda_runtime.h>
#include <cuda_fp16.h>
#include <cstdint>

// BitLinear: scale = mean|W|; Wq = round(W/(scale+eps)); y = (x @ Wq^T) * scale
// x: [8192, 4096] f32, W: [4096, 4096] f32, out: [8192, 4096] f32
//
// R7 (3rd submission; prior two rounds were broker-side container failures):
// fp32-acc HMMA (fp16-acc regressed: same HMMA rate on this die). Tile
// 128x256, 512 threads, 1 CTA/SM: halves CTA count and L2 traffic, halves
// barrier events. 3-stage cp.async.bulk pipeline from pre-blocked +
// SW128-swizzled fp16 operands.

#define EPS_F 1e-5f

__device__ float  g_partial[4096];
__device__ float  g_scale;
__device__ float  g_inv;
// g_Xa: [64 m_tiles][64 k_chunks][16 KB]  (128 rows x 64 halves, SW128)
// g_Wb: [16 n_tiles][64 k_chunks][32 KB]  (256 rows x 64 halves, SW128)
__device__ __align__(1024) __half g_Xa[8192u * 4096u];
__device__ __align__(1024) __half g_Wb[4096u * 4096u];

__host__ __device__ __forceinline__ uint32_t sw128(uint32_t off) {
    return off ^ ((off >> 3) & 0x70);
}

// ---------------------------------------------------------------- reductions
__global__ void k_absum_rows(const float* __restrict__ W) {
    int row = blockIdx.x;
    const float* p = W + (size_t)row * 4096;
    float s = 0.f;
    for (int i = threadIdx.x; i < 4096; i += 256) s += fabsf(p[i]);
    for (int o = 16; o > 0; o >>= 1) s += __shfl_down_sync(0xffffffffu, s, o);
    __shared__ float sm[8];
    if ((threadIdx.x & 31) == 0) sm[threadIdx.x >> 5] = s;
    __syncthreads();
    if (threadIdx.x < 8) {
        float v = sm[threadIdx.x];
        for (int o = 4; o > 0; o >>= 1) v += __shfl_down_sync(0xffu, v, o);
        if (threadIdx.x == 0) g_partial[row] = v;
    }
}

__global__ void k_finalize_scale() {
    float s = 0.f;
    for (int i = threadIdx.x; i < 4096; i += 256) s += g_partial[i];
    for (int o = 16; o > 0; o >>= 1) s += __shfl_down_sync(0xffffffffu, s, o);
    __shared__ float sm[8];
    if ((threadIdx.x & 31) == 0) sm[threadIdx.x >> 5] = s;
    __syncthreads();
    if (threadIdx.x < 8) {
        float v = sm[threadIdx.x];
        for (int o = 4; o > 0; o >>= 1) v += __shfl_down_sync(0xffu, v, o);
        if (threadIdx.x == 0) {
            float mean = v / 16777216.f;
            g_scale = mean;
            g_inv   = 1.f / (mean + EPS_F);
        }
    }
}

// ---------------------------------------------------------------- prepasses
// x -> fp16, blocked [m_tile=128 rows][k_chunk=64 halves], SW128
__global__ void k_conv_x(const float4* __restrict__ X4) {
    int c  = blockIdx.x * 256 + threadIdx.x;
    int m  = c >> 9;
    int k8 = c & 511;
    const float4* src = X4 + (size_t)m * 1024 + k8 * 2;
    float4 v0 = src[0], v1 = src[1];
    __half2 h0 = __floats2half2_rn(v0.x, v0.y);
    __half2 h1 = __floats2half2_rn(v0.z, v0.w);
    __half2 h2 = __floats2half2_rn(v1.x, v1.y);
    __half2 h3 = __floats2half2_rn(v1.z, v1.w);
    uint4 u;
    u.x = *reinterpret_cast<uint32_t*>(&h0);
    u.y = *reinterpret_cast<uint32_t*>(&h1);
    u.z = *reinterpret_cast<uint32_t*>(&h2);
    u.w = *reinterpret_cast<uint32_t*>(&h3);
    int k   = k8 * 8;
    int blk = ((m >> 7) << 6) + (k >> 6);
    uint32_t off = ((m & 127) << 7) + ((k & 63) << 1);
    *reinterpret_cast<uint4*>((char*)g_Xa + (size_t)blk * 16384 + sw128(off)) = u;
}

// W -> quantized fp16, blocked [n_tile=256 rows][k_chunk=64 halves], SW128
__global__ void k_quant_w(const float4* __restrict__ W4) {
    float inv = g_inv;
    int c  = blockIdx.x * 256 + threadIdx.x;
    int o  = c >> 9;
    int k8 = c & 511;
    const float4* src = W4 + (size_t)o * 1024 + k8 * 2;
    float4 v0 = src[0], v1 = src[1];
    __half2 h0 = __floats2half2_rn(rintf(v0.x * inv), rintf(v0.y * inv));
    __half2 h1 = __floats2half2_rn(rintf(v0.z * inv), rintf(v0.w * inv));
    __half2 h2 = __floats2half2_rn(rintf(v1.x * inv), rintf(v1.y * inv));
    __half2 h3 = __floats2half2_rn(rintf(v1.z * inv), rintf(v1.w * inv));
    uint4 u;
    u.x = *reinterpret_cast<uint32_t*>(&h0);
    u.y = *reinterpret_cast<uint32_t*>(&h1);
    u.z = *reinterpret_cast<uint32_t*>(&h2);
    u.w = *reinterpret_cast<uint32_t*>(&h3);
    int k   = k8 * 8;
    int blk = ((o >> 8) << 6) + (k >> 6);                 // 256-row n tiles
    uint32_t off = ((o & 255) << 7) + ((k & 63) << 1);
    *reinterpret_cast<uint4*>((char*)g_Wb + (size_t)blk * 32768 + sw128(off)) = u;
}

// ---------------------------------------------------------------- GEMM
__device__ __forceinline__ void mbar_init(uint32_t a, uint32_t cnt) {
    asm volatile("mbarrier.init.shared.b64 [%0], %1;" :: "r"(a), "r"(cnt) : "memory");
}
__device__ __forceinline__ void mbar_expect(uint32_t a, uint32_t bytes) {
    asm volatile("mbarrier.arrive.expect_tx.shared.b64 _, [%0], %1;"
                 :: "r"(a), "r"(bytes) : "memory");
}
__device__ __forceinline__ void mbar_wait(uint32_t a, uint32_t ph) {
    asm volatile(
        "{\n\t.reg .pred P;\n"
        "WL%=:\n\t"
        "mbarrier.try_wait.parity.shared.b64 P, [%0], %1, 0x989680;\n\t"
        "@P bra WD%=;\n\t"
        "bra WL%=;\n"
        "WD%=:\n\t}"
        :: "r"(a), "r"(ph) : "memory");
}
__device__ __forceinline__ void bulk_g2s(uint32_t dst, const void* src,
                                         uint32_t bytes, uint32_t mbar) {
    asm volatile(
        "cp.async.bulk.shared::cluster.global.mbarrier::complete_tx::bytes "
        "[%0], [%1], %2, [%3];"
        :: "r"(dst), "l"(src), "r"(bytes), "r"(mbar) : "memory");
}
__device__ __forceinline__ void ldm4(uint32_t addr, uint32_t& r0, uint32_t& r1,
                                     uint32_t& r2, uint32_t& r3) {
    asm volatile("ldmatrix.sync.aligned.m8n8.x4.shared.b16 {%0,%1,%2,%3}, [%4];"
                 : "=r"(r0), "=r"(r1), "=r"(r2), "=r"(r3) : "r"(addr));
}
__device__ __forceinline__ void mma16816(float& c0, float& c1, float& c2, float& c3,
                                         uint32_t a0, uint32_t a1, uint32_t a2, uint32_t a3,
                                         uint32_t b0, uint32_t b1) {
    asm volatile("mma.sync.aligned.m16n8k16.row.col.f32.f16.f16.f32 "
                 "{%0,%1,%2,%3},{%4,%5,%6,%7},{%8,%9},{%0,%1,%2,%3};"
                 : "+f"(c0), "+f"(c1), "+f"(c2), "+f"(c3)
                 : "r"(a0), "r"(a1), "r"(a2), "r"(a3), "r"(b0), "r"(b1));
}

#define NSTAGE 3
#define A_STG 16384
#define B_STG 32768
#define CTRL  1024
#define SMEM_TOTAL (CTRL + NSTAGE * (A_STG + B_STG))   // 148480

__global__ void __launch_bounds__(512) k_gemm(float* __restrict__ out) {
    extern __shared__ __align__(1024) char smem[];
    uint32_t sb = (uint32_t)__cvta_generic_to_shared(smem);
    const int tid    = threadIdx.x;
    const int lane   = tid & 31;
    const int wid    = tid >> 5;       // 0..15
    const int warp_m = wid >> 2;       // 0..3 -> 32-row slab
    const int warp_n = wid & 3;        // 0..3 -> 64-col slab
    const int bn     = blockIdx.x;     // 0..15 (256-col tile)
    const int bm     = blockIdx.y;     // 0..63 (128-row tile)

    const uint32_t sA = sb + CTRL;
    const uint32_t sB = sb + CTRL + NSTAGE * A_STG;
    const char* gA = (const char*)g_Xa + (size_t)bm * 64 * A_STG;
    const char* gB = (const char*)g_Wb + (size_t)bn * 64 * B_STG;

    if (tid == 0)
        for (int s = 0; s < NSTAGE; s++) mbar_init(sb + s * 8, 1);
    __syncthreads();

    if (tid == 0) {
#pragma unroll
        for (int j = 0; j < NSTAGE - 1; j++) {
            uint32_t fb = sb + j * 8;
            mbar_expect(fb, A_STG + B_STG);
            bulk_g2s(sA + j * A_STG, gA + (size_t)j * A_STG, A_STG, fb);
            bulk_g2s(sB + j * B_STG, gB + (size_t)j * B_STG, B_STG, fb);
        }
    }

    float acc[2][8][4];
#pragma unroll
    for (int mi = 0; mi < 2; mi++)
#pragma unroll
        for (int ni = 0; ni < 8; ni++)
#pragma unroll
            for (int r = 0; r < 4; r++) acc[mi][ni][r] = 0.f;

    for (int i = 0; i < 64; ++i) {
        const int s = i % NSTAGE;
        mbar_wait(sb + s * 8, (i / NSTAGE) & 1);
        __syncthreads();
        if (tid == 0 && i + NSTAGE - 1 < 64) {
            int j = i + NSTAGE - 1;
            int t = j % NSTAGE;
            uint32_t fb = sb + t * 8;
            mbar_expect(fb, A_STG + B_STG);
            bulk_g2s(sA + t * A_STG, gA + (size_t)j * A_STG, A_STG, fb);
            bulk_g2s(sB + t * B_STG, gB + (size_t)j * B_STG, B_STG, fb);
        }
        const uint32_t a_base = sA + s * A_STG;
        const uint32_t b_base = sB + s * B_STG;

#pragma unroll
        for (int ks = 0; ks < 4; ++ks) {
            uint32_t a[2][4];
#pragma unroll
            for (int mi = 0; mi < 2; mi++) {
                int r   = warp_m * 32 + mi * 16 + (lane & 15);
                int col = ks * 16 + (lane >> 4) * 8;
                ldm4(a_base + sw128((uint32_t)(r * 128 + col * 2)),
                     a[mi][0], a[mi][1], a[mi][2], a[mi][3]);
            }
            uint32_t b[8][2];
#pragma unroll
            for (int np = 0; np < 4; np++) {
                int n   = warp_n * 64 + np * 16 + (lane >> 4) * 8 + (lane & 7);
                int col = ks * 16 + ((lane >> 3) & 1) * 8;
                uint32_t r0, r1, r2, r3;
                ldm4(b_base + sw128((uint32_t)(n * 128 + col * 2)), r0, r1, r2, r3);
                b[np * 2][0]     = r0;  b[np * 2][1]     = r1;
                b[np * 2 + 1][0] = r2;  b[np * 2 + 1][1] = r3;
            }
#pragma unroll
            for (int mi = 0; mi < 2; mi++)
#pragma unroll
                for (int ni = 0; ni < 8; ni++)
                    mma16816(acc[mi][ni][0], acc[mi][ni][1], acc[mi][ni][2], acc[mi][ni][3],
                             a[mi][0], a[mi][1], a[mi][2], a[mi][3],
                             b[ni][0], b[ni][1]);
        }
    }

    const float scale = g_scale;
#pragma unroll
    for (int mi = 0; mi < 2; mi++) {
        int row0 = bm * 128 + warp_m * 32 + mi * 16 + (lane >> 2);
#pragma unroll
        for (int ni = 0; ni < 8; ni++) {
            int col = bn * 256 + warp_n * 64 + ni * 8 + (lane & 3) * 2;
            float2 v0 = make_float2(acc[mi][ni][0] * scale, acc[mi][ni][1] * scale);
            float2 v1 = make_float2(acc[mi][ni][2] * scale, acc[mi][ni][3] * scale);
            *(float2*)&out[(size_t)row0 * 4096 + col]       = v0;
            *(float2*)&out[(size_t)(row0 + 8) * 4096 + col] = v1;
        }
    }
}

// ---------------------------------------------------------------- launch
extern "C" void kernel_launch(void* const* d_in, const int* in_sizes, int n_in,
                              void* d_out, int out_size) {
    const float* x = (const float*)d_in[0];
    const float* W = (const float*)d_in[1];
    float* out = (float*)d_out;

    k_absum_rows<<<4096, 256>>>(W);
    k_finalize_scale<<<1, 256>>>();
    k_conv_x<<<16384, 256>>>((const float4*)x);
    k_quant_w<<<8192, 256>>>((const float4*)W);

    cudaFuncSetAttribute(k_gemm, cudaFuncAttributeMaxDynamicSharedMemorySize, SMEM_TOTAL);
    dim3 grid(16, 64);   // (N/256, M/128)
    k_gemm<<<grid, 512, SMEM_TOTAL>>>(out);
}

// round 10
// speedup vs baseline: 1.1832x; 1.1305x over previous
#include <cuda_runtime.h>
#include <cuda_fp16.h>
#include <cstdint>

// BitLinear: scale = mean|W|; Wq = round(W/(scale+eps)); y = (x @ Wq^T) * scale
// x: [8192, 4096] f32, W: [4096, 4096] f32, out: [8192, 4096] f32
//
// R10: back to R3's proven config (128x128x64, 256 thr, NSTAGE=3, 2 CTA/SM),
// but replace per-iteration __syncthreads with per-stage EMPTY mbarriers
// (arrive-count 8): warps free stages independently, producer waits only on
// the true dependency. fp32-acc HMMA (fp16-acc and 1-CTA/SM fat tiles both
// measured slower).

#define EPS_F 1e-5f

__device__ float  g_partial[4096];
__device__ float  g_scale;
__device__ float  g_inv;
// blocked+swizzled fp16 operands, 16KB blocks = [128 rows][64 halves] SW128
__device__ __align__(1024) __half g_Xa[8192u * 4096u];   // [64 m][64 k] blocks
__device__ __align__(1024) __half g_Wb[4096u * 4096u];   // [32 n][64 k] blocks

__host__ __device__ __forceinline__ uint32_t sw128(uint32_t off) {
    return off ^ ((off >> 3) & 0x70);
}

// ---------------------------------------------------------------- reductions
__global__ void k_absum_rows(const float4* __restrict__ W4) {
    int row = blockIdx.x;
    const float4* p = W4 + (size_t)row * 1024;
    float s = 0.f;
    for (int i = threadIdx.x; i < 1024; i += 256) {
        float4 v = p[i];
        s += fabsf(v.x) + fabsf(v.y) + fabsf(v.z) + fabsf(v.w);
    }
    for (int o = 16; o > 0; o >>= 1) s += __shfl_down_sync(0xffffffffu, s, o);
    __shared__ float sm[8];
    if ((threadIdx.x & 31) == 0) sm[threadIdx.x >> 5] = s;
    __syncthreads();
    if (threadIdx.x < 8) {
        float v = sm[threadIdx.x];
        for (int o = 4; o > 0; o >>= 1) v += __shfl_down_sync(0xffu, v, o);
        if (threadIdx.x == 0) g_partial[row] = v;
    }
}

__global__ void k_finalize_scale() {
    float s = 0.f;
    for (int i = threadIdx.x; i < 4096; i += 256) s += g_partial[i];
    for (int o = 16; o > 0; o >>= 1) s += __shfl_down_sync(0xffffffffu, s, o);
    __shared__ float sm[8];
    if ((threadIdx.x & 31) == 0) sm[threadIdx.x >> 5] = s;
    __syncthreads();
    if (threadIdx.x < 8) {
        float v = sm[threadIdx.x];
        for (int o = 4; o > 0; o >>= 1) v += __shfl_down_sync(0xffu, v, o);
        if (threadIdx.x == 0) {
            float mean = v / 16777216.f;
            g_scale = mean;
            g_inv   = 1.f / (mean + EPS_F);
        }
    }
}

// ---------------------------------------------------------------- prepasses
// x -> fp16, blocked [m_tile=128 rows][k_chunk=64 halves], SW128 swizzled
__global__ void k_conv_x(const float4* __restrict__ X4) {
    int c  = blockIdx.x * 256 + threadIdx.x;
    int m  = c >> 9;
    int k8 = c & 511;
    const float4* src = X4 + (size_t)m * 1024 + k8 * 2;
    float4 v0 = src[0], v1 = src[1];
    __half2 h0 = __floats2half2_rn(v0.x, v0.y);
    __half2 h1 = __floats2half2_rn(v0.z, v0.w);
    __half2 h2 = __floats2half2_rn(v1.x, v1.y);
    __half2 h3 = __floats2half2_rn(v1.z, v1.w);
    uint4 u;
    u.x = *reinterpret_cast<uint32_t*>(&h0);
    u.y = *reinterpret_cast<uint32_t*>(&h1);
    u.z = *reinterpret_cast<uint32_t*>(&h2);
    u.w = *reinterpret_cast<uint32_t*>(&h3);
    int k   = k8 * 8;
    int blk = ((m >> 7) << 6) + (k >> 6);
    uint32_t off = ((m & 127) << 7) + ((k & 63) << 1);
    *reinterpret_cast<uint4*>((char*)g_Xa + (size_t)blk * 16384 + sw128(off)) = u;
}

// W -> quantized fp16, blocked [n_tile=128 rows][k_chunk=64 halves], SW128
__global__ void k_quant_w(const float4* __restrict__ W4) {
    float inv = g_inv;
    int c  = blockIdx.x * 256 + threadIdx.x;
    int o  = c >> 9;
    int k8 = c & 511;
    const float4* src = W4 + (size_t)o * 1024 + k8 * 2;
    float4 v0 = src[0], v1 = src[1];
    __half2 h0 = __floats2half2_rn(rintf(v0.x * inv), rintf(v0.y * inv));
    __half2 h1 = __floats2half2_rn(rintf(v0.z * inv), rintf(v0.w * inv));
    __half2 h2 = __floats2half2_rn(rintf(v1.x * inv), rintf(v1.y * inv));
    __half2 h3 = __floats2half2_rn(rintf(v1.z * inv), rintf(v1.w * inv));
    uint4 u;
    u.x = *reinterpret_cast<uint32_t*>(&h0);
    u.y = *reinterpret_cast<uint32_t*>(&h1);
    u.z = *reinterpret_cast<uint32_t*>(&h2);
    u.w = *reinterpret_cast<uint32_t*>(&h3);
    int k   = k8 * 8;
    int blk = ((o >> 7) << 6) + (k >> 6);
    uint32_t off = ((o & 127) << 7) + ((k & 63) << 1);
    *reinterpret_cast<uint4*>((char*)g_Wb + (size_t)blk * 16384 + sw128(off)) = u;
}

// ---------------------------------------------------------------- GEMM
__device__ __forceinline__ void mbar_init(uint32_t a, uint32_t cnt) {
    asm volatile("mbarrier.init.shared.b64 [%0], %1;" :: "r"(a), "r"(cnt) : "memory");
}
__device__ __forceinline__ void mbar_expect(uint32_t a, uint32_t bytes) {
    asm volatile("mbarrier.arrive.expect_tx.shared.b64 _, [%0], %1;"
                 :: "r"(a), "r"(bytes) : "memory");
}
__device__ __forceinline__ void mbar_arrive(uint32_t a) {
    asm volatile("mbarrier.arrive.shared.b64 _, [%0];" :: "r"(a) : "memory");
}
__device__ __forceinline__ void mbar_wait(uint32_t a, uint32_t ph) {
    asm volatile(
        "{\n\t.reg .pred P;\n"
        "WL%=:\n\t"
        "mbarrier.try_wait.parity.shared.b64 P, [%0], %1, 0x989680;\n\t"
        "@P bra WD%=;\n\t"
        "bra WL%=;\n"
        "WD%=:\n\t}"
        :: "r"(a), "r"(ph) : "memory");
}
__device__ __forceinline__ void bulk_g2s(uint32_t dst, const void* src,
                                         uint32_t bytes, uint32_t mbar) {
    asm volatile(
        "cp.async.bulk.shared::cluster.global.mbarrier::complete_tx::bytes "
        "[%0], [%1], %2, [%3];"
        :: "r"(dst), "l"(src), "r"(bytes), "r"(mbar) : "memory");
}
__device__ __forceinline__ void ldm4(uint32_t addr, uint32_t& r0, uint32_t& r1,
                                     uint32_t& r2, uint32_t& r3) {
    asm volatile("ldmatrix.sync.aligned.m8n8.x4.shared.b16 {%0,%1,%2,%3}, [%4];"
                 : "=r"(r0), "=r"(r1), "=r"(r2), "=r"(r3) : "r"(addr));
}
__device__ __forceinline__ void mma16816(float& c0, float& c1, float& c2, float& c3,
                                         uint32_t a0, uint32_t a1, uint32_t a2, uint32_t a3,
                                         uint32_t b0, uint32_t b1) {
    asm volatile("mma.sync.aligned.m16n8k16.row.col.f32.f16.f16.f32 "
                 "{%0,%1,%2,%3},{%4,%5,%6,%7},{%8,%9},{%0,%1,%2,%3};"
                 : "+f"(c0), "+f"(c1), "+f"(c2), "+f"(c3)
                 : "r"(a0), "r"(a1), "r"(a2), "r"(a3), "r"(b0), "r"(b1));
}

#define NSTAGE 3
#define STG 16384
#define CTRL 1024
#define SMEM_TOTAL (CTRL + NSTAGE * 2 * STG)   // 99328 -> 2 CTAs/SM

__global__ void __launch_bounds__(256, 2) k_gemm(float* __restrict__ out) {
    extern __shared__ __align__(1024) char smem[];
    uint32_t sb = (uint32_t)__cvta_generic_to_shared(smem);
    const int tid    = threadIdx.x;
    const int lane   = tid & 31;
    const int wid    = tid >> 5;
    const int warp_m = wid >> 2;     // 0..1 -> 64-row slab
    const int warp_n = wid & 3;      // 0..3 -> 32-col slab
    const int bn     = blockIdx.x;   // 0..31
    const int bm     = blockIdx.y;   // 0..63

    // ctrl: full[s] @ sb+8s, empty[s] @ sb+24+8s
    const uint32_t sA = sb + CTRL;
    const uint32_t sB = sb + CTRL + NSTAGE * STG;
    const char* gA = (const char*)g_Xa + (size_t)bm * 64 * STG;
    const char* gB = (const char*)g_Wb + (size_t)bn * 64 * STG;

    if (tid == 0) {
        for (int s = 0; s < NSTAGE; s++) {
            mbar_init(sb + s * 8, 1);        // full: producer expect_tx
            mbar_init(sb + 24 + s * 8, 8);   // empty: one arrive per warp
        }
    }
    __syncthreads();

    if (tid == 0) {
#pragma unroll
        for (int j = 0; j < NSTAGE - 1; j++) {
            uint32_t fb = sb + j * 8;
            mbar_expect(fb, 2 * STG);
            bulk_g2s(sA + j * STG, gA + (size_t)j * STG, STG, fb);
            bulk_g2s(sB + j * STG, gB + (size_t)j * STG, STG, fb);
        }
    }

    float acc[4][4][4];
#pragma unroll
    for (int mi = 0; mi < 4; mi++)
#pragma unroll
        for (int ni = 0; ni < 4; ni++)
#pragma unroll
            for (int r = 0; r < 4; r++) acc[mi][ni][r] = 0.f;

    for (int i = 0; i < 64; ++i) {
        const int s = i % NSTAGE;
        // producer: issue stage j = i + NSTAGE-1 once it is free
        if (tid == 0 && i + NSTAGE - 1 < 64) {
            int j = i + NSTAGE - 1;
            int t = j % NSTAGE;
            if (j >= NSTAGE)
                mbar_wait(sb + 24 + t * 8, ((j - NSTAGE) / NSTAGE) & 1);
            uint32_t fb = sb + t * 8;
            mbar_expect(fb, 2 * STG);
            bulk_g2s(sA + t * STG, gA + (size_t)j * STG, STG, fb);
            bulk_g2s(sB + t * STG, gB + (size_t)j * STG, STG, fb);
        }
        mbar_wait(sb + s * 8, (i / NSTAGE) & 1);
        const uint32_t a_base = sA + s * STG;
        const uint32_t b_base = sB + s * STG;

#pragma unroll
        for (int ks = 0; ks < 4; ++ks) {
            uint32_t a[4][4];
#pragma unroll
            for (int mi = 0; mi < 4; mi++) {
                int r   = warp_m * 64 + mi * 16 + (lane & 15);
                int col = ks * 16 + (lane >> 4) * 8;
                ldm4(a_base + sw128((uint32_t)(r * 128 + col * 2)),
                     a[mi][0], a[mi][1], a[mi][2], a[mi][3]);
            }
            uint32_t b[4][2];
#pragma unroll
            for (int np = 0; np < 2; np++) {
                int n   = warp_n * 32 + np * 16 + (lane >> 4) * 8 + (lane & 7);
                int col = ks * 16 + ((lane >> 3) & 1) * 8;
                uint32_t r0, r1, r2, r3;
                ldm4(b_base + sw128((uint32_t)(n * 128 + col * 2)), r0, r1, r2, r3);
                b[np * 2][0]     = r0;  b[np * 2][1]     = r1;
                b[np * 2 + 1][0] = r2;  b[np * 2 + 1][1] = r3;
            }
#pragma unroll
            for (int mi = 0; mi < 4; mi++)
#pragma unroll
                for (int ni = 0; ni < 4; ni++)
                    mma16816(acc[mi][ni][0], acc[mi][ni][1], acc[mi][ni][2], acc[mi][ni][3],
                             a[mi][0], a[mi][1], a[mi][2], a[mi][3],
                             b[ni][0], b[ni][1]);
        }
        // this warp is done reading stage s
        if (lane == 0) mbar_arrive(sb + 24 + s * 8);
    }

    const float scale = g_scale;
#pragma unroll
    for (int mi = 0; mi < 4; mi++) {
        int row0 = bm * 128 + warp_m * 64 + mi * 16 + (lane >> 2);
#pragma unroll
        for (int ni = 0; ni < 4; ni++) {
            int col = bn * 128 + warp_n * 32 + ni * 8 + (lane & 3) * 2;
            float2 v0 = make_float2(acc[mi][ni][0] * scale, acc[mi][ni][1] * scale);
            float2 v1 = make_float2(acc[mi][ni][2] * scale, acc[mi][ni][3] * scale);
            *(float2*)&out[(size_t)row0 * 4096 + col]       = v0;
            *(float2*)&out[(size_t)(row0 + 8) * 4096 + col] = v1;
        }
    }
}

// ---------------------------------------------------------------- launch
extern "C" void kernel_launch(void* const* d_in, const int* in_sizes, int n_in,
                              void* d_out, int out_size) {
    const float* x = (const float*)d_in[0];
    const float* W = (const float*)d_in[1];
    float* out = (float*)d_out;

    k_absum_rows<<<4096, 256>>>((const float4*)W);
    k_finalize_scale<<<1, 256>>>();
    k_conv_x<<<16384, 256>>>((const float4*)x);
    k_quant_w<<<8192, 256>>>((const float4*)W);

    cudaFuncSetAttribute(k_gemm, cudaFuncAttributeMaxDynamicSharedMemorySize, SMEM_TOTAL);
    dim3 grid(32, 64);   // (N/128, M/128)
    k_gemm<<<grid, 256, SMEM_TOTAL>>>(out);
}

// round 15
// speedup vs baseline: 1.1955x; 1.0104x over previous
#include <cuda_runtime.h>
#include <cuda_fp16.h>
#include <cstdint>

// BitLinear: scale = mean|W|; Wq = round(W/(scale+eps)); y = (x @ Wq^T) * scale
// x: [8192, 4096] f32, W: [4096, 4096] f32, out: [8192, 4096] f32
//
// R11 (2nd submission; prior round was a broker-side container failure):
// smem-bandwidth attack. Same 128x128x64 CTA tile / NSTAGE=3 / 2 CTA/SM as
// R3, but 4 warps with 64x64 warp tiles: A-fragment duplication 4x -> 2x,
// ldmatrix smem traffic -33%. fp32-acc HMMA, cp.async.bulk producer,
// R3's __syncthreads pipeline (best measured variant).

#define EPS_F 1e-5f

__device__ float  g_partial[4096];
__device__ float  g_scale;
__device__ float  g_inv;
// blocked+swizzled fp16 operands, 16KB blocks = [128 rows][64 halves] SW128
__device__ __align__(1024) __half g_Xa[8192u * 4096u];   // [64 m][64 k] blocks
__device__ __align__(1024) __half g_Wb[4096u * 4096u];   // [32 n][64 k] blocks

__host__ __device__ __forceinline__ uint32_t sw128(uint32_t off) {
    return off ^ ((off >> 3) & 0x70);
}

// ---------------------------------------------------------------- reductions
__global__ void k_absum_rows(const float4* __restrict__ W4) {
    int row = blockIdx.x;
    const float4* p = W4 + (size_t)row * 1024;
    float s = 0.f;
    for (int i = threadIdx.x; i < 1024; i += 256) {
        float4 v = p[i];
        s += fabsf(v.x) + fabsf(v.y) + fabsf(v.z) + fabsf(v.w);
    }
    for (int o = 16; o > 0; o >>= 1) s += __shfl_down_sync(0xffffffffu, s, o);
    __shared__ float sm[8];
    if ((threadIdx.x & 31) == 0) sm[threadIdx.x >> 5] = s;
    __syncthreads();
    if (threadIdx.x < 8) {
        float v = sm[threadIdx.x];
        for (int o = 4; o > 0; o >>= 1) v += __shfl_down_sync(0xffu, v, o);
        if (threadIdx.x == 0) g_partial[row] = v;
    }
}

__global__ void k_finalize_scale() {
    float s = 0.f;
    for (int i = threadIdx.x; i < 4096; i += 256) s += g_partial[i];
    for (int o = 16; o > 0; o >>= 1) s += __shfl_down_sync(0xffffffffu, s, o);
    __shared__ float sm[8];
    if ((threadIdx.x & 31) == 0) sm[threadIdx.x >> 5] = s;
    __syncthreads();
    if (threadIdx.x < 8) {
        float v = sm[threadIdx.x];
        for (int o = 4; o > 0; o >>= 1) v += __shfl_down_sync(0xffu, v, o);
        if (threadIdx.x == 0) {
            float mean = v / 16777216.f;
            g_scale = mean;
            g_inv   = 1.f / (mean + EPS_F);
        }
    }
}

// ---------------------------------------------------------------- prepasses
__global__ void k_conv_x(const float4* __restrict__ X4) {
    int c  = blockIdx.x * 256 + threadIdx.x;
    int m  = c >> 9;
    int k8 = c & 511;
    const float4* src = X4 + (size_t)m * 1024 + k8 * 2;
    float4 v0 = src[0], v1 = src[1];
    __half2 h0 = __floats2half2_rn(v0.x, v0.y);
    __half2 h1 = __floats2half2_rn(v0.z, v0.w);
    __half2 h2 = __floats2half2_rn(v1.x, v1.y);
    __half2 h3 = __floats2half2_rn(v1.z, v1.w);
    uint4 u;
    u.x = *reinterpret_cast<uint32_t*>(&h0);
    u.y = *reinterpret_cast<uint32_t*>(&h1);
    u.z = *reinterpret_cast<uint32_t*>(&h2);
    u.w = *reinterpret_cast<uint32_t*>(&h3);
    int k   = k8 * 8;
    int blk = ((m >> 7) << 6) + (k >> 6);
    uint32_t off = ((m & 127) << 7) + ((k & 63) << 1);
    *reinterpret_cast<uint4*>((char*)g_Xa + (size_t)blk * 16384 + sw128(off)) = u;
}

__global__ void k_quant_w(const float4* __restrict__ W4) {
    float inv = g_inv;
    int c  = blockIdx.x * 256 + threadIdx.x;
    int o  = c >> 9;
    int k8 = c & 511;
    const float4* src = W4 + (size_t)o * 1024 + k8 * 2;
    float4 v0 = src[0], v1 = src[1];
    __half2 h0 = __floats2half2_rn(rintf(v0.x * inv), rintf(v0.y * inv));
    __half2 h1 = __floats2half2_rn(rintf(v0.z * inv), rintf(v0.w * inv));
    __half2 h2 = __floats2half2_rn(rintf(v1.x * inv), rintf(v1.y * inv));
    __half2 h3 = __floats2half2_rn(rintf(v1.z * inv), rintf(v1.w * inv));
    uint4 u;
    u.x = *reinterpret_cast<uint32_t*>(&h0);
    u.y = *reinterpret_cast<uint32_t*>(&h1);
    u.z = *reinterpret_cast<uint32_t*>(&h2);
    u.w = *reinterpret_cast<uint32_t*>(&h3);
    int k   = k8 * 8;
    int blk = ((o >> 7) << 6) + (k >> 6);
    uint32_t off = ((o & 127) << 7) + ((k & 63) << 1);
    *reinterpret_cast<uint4*>((char*)g_Wb + (size_t)blk * 16384 + sw128(off)) = u;
}

// ---------------------------------------------------------------- GEMM
__device__ __forceinline__ void mbar_init(uint32_t a, uint32_t cnt) {
    asm volatile("mbarrier.init.shared.b64 [%0], %1;" :: "r"(a), "r"(cnt) : "memory");
}
__device__ __forceinline__ void mbar_expect(uint32_t a, uint32_t bytes) {
    asm volatile("mbarrier.arrive.expect_tx.shared.b64 _, [%0], %1;"
                 :: "r"(a), "r"(bytes) : "memory");
}
__device__ __forceinline__ void mbar_wait(uint32_t a, uint32_t ph) {
    asm volatile(
        "{\n\t.reg .pred P;\n"
        "WL%=:\n\t"
        "mbarrier.try_wait.parity.shared.b64 P, [%0], %1, 0x989680;\n\t"
        "@P bra WD%=;\n\t"
        "bra WL%=;\n"
        "WD%=:\n\t}"
        :: "r"(a), "r"(ph) : "memory");
}
__device__ __forceinline__ void bulk_g2s(uint32_t dst, const void* src,
                                         uint32_t bytes, uint32_t mbar) {
    asm volatile(
        "cp.async.bulk.shared::cluster.global.mbarrier::complete_tx::bytes "
        "[%0], [%1], %2, [%3];"
        :: "r"(dst), "l"(src), "r"(bytes), "r"(mbar) : "memory");
}
__device__ __forceinline__ void ldm4(uint32_t addr, uint32_t& r0, uint32_t& r1,
                                     uint32_t& r2, uint32_t& r3) {
    asm volatile("ldmatrix.sync.aligned.m8n8.x4.shared.b16 {%0,%1,%2,%3}, [%4];"
                 : "=r"(r0), "=r"(r1), "=r"(r2), "=r"(r3) : "r"(addr));
}
__device__ __forceinline__ void mma16816(float& c0, float& c1, float& c2, float& c3,
                                         uint32_t a0, uint32_t a1, uint32_t a2, uint32_t a3,
                                         uint32_t b0, uint32_t b1) {
    asm volatile("mma.sync.aligned.m16n8k16.row.col.f32.f16.f16.f32 "
                 "{%0,%1,%2,%3},{%4,%5,%6,%7},{%8,%9},{%0,%1,%2,%3};"
                 : "+f"(c0), "+f"(c1), "+f"(c2), "+f"(c3)
                 : "r"(a0), "r"(a1), "r"(a2), "r"(a3), "r"(b0), "r"(b1));
}

#define NSTAGE 3
#define STG 16384
#define CTRL 1024
#define SMEM_TOTAL (CTRL + NSTAGE * 2 * STG)   // 99328 -> 2 CTAs/SM

__global__ void __launch_bounds__(128, 2) k_gemm(float* __restrict__ out) {
    extern __shared__ __align__(1024) char smem[];
    uint32_t sb = (uint32_t)__cvta_generic_to_shared(smem);
    const int tid    = threadIdx.x;
    const int lane   = tid & 31;
    const int wid    = tid >> 5;     // 0..3
    const int warp_m = wid >> 1;     // 0..1 -> 64-row slab
    const int warp_n = wid & 1;      // 0..1 -> 64-col slab
    const int bn     = blockIdx.x;   // 0..31
    const int bm     = blockIdx.y;   // 0..63

    const uint32_t sA = sb + CTRL;
    const uint32_t sB = sb + CTRL + NSTAGE * STG;
    const char* gA = (const char*)g_Xa + (size_t)bm * 64 * STG;
    const char* gB = (const char*)g_Wb + (size_t)bn * 64 * STG;

    if (tid == 0)
        for (int s = 0; s < NSTAGE; s++) mbar_init(sb + s * 8, 1);
    __syncthreads();

    if (tid == 0) {
#pragma unroll
        for (int j = 0; j < NSTAGE - 1; j++) {
            uint32_t fb = sb + j * 8;
            mbar_expect(fb, 2 * STG);
            bulk_g2s(sA + j * STG, gA + (size_t)j * STG, STG, fb);
            bulk_g2s(sB + j * STG, gB + (size_t)j * STG, STG, fb);
        }
    }

    float acc[4][8][4];
#pragma unroll
    for (int mi = 0; mi < 4; mi++)
#pragma unroll
        for (int ni = 0; ni < 8; ni++)
#pragma unroll
            for (int r = 0; r < 4; r++) acc[mi][ni][r] = 0.f;

    for (int i = 0; i < 64; ++i) {
        const int s = i % NSTAGE;
        mbar_wait(sb + s * 8, (i / NSTAGE) & 1);
        __syncthreads();
        if (tid == 0 && i + NSTAGE - 1 < 64) {
            int j = i + NSTAGE - 1;
            int t = j % NSTAGE;
            uint32_t fb = sb + t * 8;
            mbar_expect(fb, 2 * STG);
            bulk_g2s(sA + t * STG, gA + (size_t)j * STG, STG, fb);
            bulk_g2s(sB + t * STG, gB + (size_t)j * STG, STG, fb);
        }
        const uint32_t a_base = sA + s * STG;
        const uint32_t b_base = sB + s * STG;

#pragma unroll
        for (int ks = 0; ks < 4; ++ks) {
            uint32_t a[4][4];
#pragma unroll
            for (int mi = 0; mi < 4; mi++) {
                int r   = warp_m * 64 + mi * 16 + (lane & 15);
                int col = ks * 16 + (lane >> 4) * 8;
                ldm4(a_base + sw128((uint32_t)(r * 128 + col * 2)),
                     a[mi][0], a[mi][1], a[mi][2], a[mi][3]);
            }
            uint32_t b[8][2];
#pragma unroll
            for (int np = 0; np < 4; np++) {
                int n   = warp_n * 64 + np * 16 + (lane >> 4) * 8 + (lane & 7);
                int col = ks * 16 + ((lane >> 3) & 1) * 8;
                uint32_t r0, r1, r2, r3;
                ldm4(b_base + sw128((uint32_t)(n * 128 + col * 2)), r0, r1, r2, r3);
                b[np * 2][0]     = r0;  b[np * 2][1]     = r1;
                b[np * 2 + 1][0] = r2;  b[np * 2 + 1][1] = r3;
            }
#pragma unroll
            for (int mi = 0; mi < 4; mi++)
#pragma unroll
                for (int ni = 0; ni < 8; ni++)
                    mma16816(acc[mi][ni][0], acc[mi][ni][1], acc[mi][ni][2], acc[mi][ni][3],
                             a[mi][0], a[mi][1], a[mi][2], a[mi][3],
                             b[ni][0], b[ni][1]);
        }
        __syncthreads();
    }

    const float scale = g_scale;
#pragma unroll
    for (int mi = 0; mi < 4; mi++) {
        int row0 = bm * 128 + warp_m * 64 + mi * 16 + (lane >> 2);
#pragma unroll
        for (int ni = 0; ni < 8; ni++) {
            int col = bn * 128 + warp_n * 64 + ni * 8 + (lane & 3) * 2;
            float2 v0 = make_float2(acc[mi][ni][0] * scale, acc[mi][ni][1] * scale);
            float2 v1 = make_float2(acc[mi][ni][2] * scale, acc[mi][ni][3] * scale);
            *(float2*)&out[(size_t)row0 * 4096 + col]       = v0;
            *(float2*)&out[(size_t)(row0 + 8) * 4096 + col] = v1;
        }
    }
}

// ---------------------------------------------------------------- launch
extern "C" void kernel_launch(void* const* d_in, const int* in_sizes, int n_in,
                              void* d_out, int out_size) {
    const float* x = (const float*)d_in[0];
    const float* W = (const float*)d_in[1];
    float* out = (float*)d_out;

    k_absum_rows<<<4096, 256>>>((const float4*)W);
    k_finalize_scale<<<1, 256>>>();
    k_conv_x<<<16384, 256>>>((const float4*)x);
    k_quant_w<<<8192, 256>>>((const float4*)W);

    cudaFuncSetAttribute(k_gemm, cudaFuncAttributeMaxDynamicSharedMemorySize, SMEM_TOTAL);
    dim3 grid(32, 64);   // (N/128, M/128)
    k_gemm<<<grid, 128, SMEM_TOTAL>>>(out);
}